// round 12
// baseline (speedup 1.0000x reference)
#include <cuda_runtime.h>
#include <cstddef>

#define BSZ 8
#define SEQLEN 2048
#define VOCAB 32000
#define BOS 1
#define V4 (VOCAB / 4)               // 8000 float4 per row
#define FILL_BLOCKS (BSZ * SEQLEN)   // 16384 rows, one block each
#define THREADS 256
#define MAJ_THREADS 1024

// Global scratch (allocation-free rule: __device__ globals only)
__device__ int g_hist[BSZ][VOCAB];   // 1 MB
__device__ int g_pred[BSZ];

// ---------------------------------------------------------------------------
// Kernel A: per-batch majority, vectorized (int4 zero + int4 argmax scan).
// Triggers programmatic launch completion at entry so the fill grid can
// launch and stream concurrently; but stays cheap (~1.5-2us) in case the
// graph replay serializes the PDL pair.
// ---------------------------------------------------------------------------
__global__ __launch_bounds__(MAJ_THREADS) void majority_kernel(const int* __restrict__ ids) {
#if __CUDA_ARCH__ >= 900
    cudaTriggerProgrammaticLaunchCompletion();   // let fill grid launch now
#endif
    const int b = blockIdx.x;
    const int t = threadIdx.x;
    int* __restrict__ hist = g_hist[b];
    int4* __restrict__ hist4 = (int4*)hist;      // VOCAB/4 = 8000 int4

    // zero histogram row: 8000 int4 / 1024 threads = 8 iters, STG.128
    const int4 z4 = make_int4(0, 0, 0, 0);
    for (int v = t; v < VOCAB / 4; v += MAJ_THREADS) hist4[v] = z4;
    __syncthreads();

    // accumulate valid tokens (exclude pad=0 and BOS=1): 2048 -> 2 per thread
    const int* row = ids + (size_t)b * SEQLEN;
    for (int s = t; s < SEQLEN; s += MAJ_THREADS) {
        int tok = row[s];
        if (tok != 0 && tok != BOS) atomicAdd(&hist[tok], 1);
    }
    __syncthreads();

    // argmax, tie -> lowest index: key = (count<<15) | (32767 - v)
    // vectorized LDG.128 scan over 8000 int4
    __shared__ int best;
    if (t == 0) best = 0;
    __syncthreads();

    int lb = 0;
    for (int v4 = t; v4 < VOCAB / 4; v4 += MAJ_THREADS) {
        int4 c = hist4[v4];
        int v = v4 * 4;
        int k0 = (c.x << 15) | (32767 - v);
        int k1 = (c.y << 15) | (32767 - (v + 1));
        int k2 = (c.z << 15) | (32767 - (v + 2));
        int k3 = (c.w << 15) | (32767 - (v + 3));
        lb = max(lb, max(max(k0, k1), max(k2, k3)));
    }
    atomicMax(&best, lb);
    __syncthreads();

    if (t == 0) {
        int cnt = best >> 15;
        int v = 32767 - (best & 32767);
        g_pred[b] = (cnt > 0) ? v : BOS;  // no valid tokens -> BOS
    }
}

// ---------------------------------------------------------------------------
// Kernel B (UNCHANGED from R8 winner — proven 93.6% DRAM): streaming fill,
// one (b,s) row per block. Pure -6 STG.128 stream (no cache hints, no
// atomics, no fences), then HW-backed PDL wait, then thread 0 rewrites the
// aligned 32B sector holding the pred element (full-sector write, no RMW).
// ---------------------------------------------------------------------------
__global__ __launch_bounds__(THREADS) void fill_kernel(float4* __restrict__ out) {
    const int r = blockIdx.x;            // row index in [0, 16384)
    const int t = threadIdx.x;
    const int b = r >> 11;               // batch = r / SEQLEN

    const float4 neg = make_float4(-6.0f, -6.0f, -6.0f, -6.0f);
    float4* __restrict__ dst = out + (size_t)r * V4;

    for (int i = t; i < V4; i += THREADS) {
        dst[i] = neg;
    }

#if __CUDA_ARCH__ >= 900
    cudaGridDependencySynchronize();     // majority grid complete + visible
#endif
    __syncthreads();                     // order own -6 stores before patch

    if (t == 0) {
        const int p    = g_pred[b];
        const int base = p & ~7;         // 8-float (32B) aligned window
        const int c    = p & 7;

        float4 lo = neg, hi = neg;
        if      (c == 0) lo.x = 6.0f;
        else if (c == 1) lo.y = 6.0f;
        else if (c == 2) lo.z = 6.0f;
        else if (c == 3) lo.w = 6.0f;
        else if (c == 4) hi.x = 6.0f;
        else if (c == 5) hi.y = 6.0f;
        else if (c == 6) hi.z = 6.0f;
        else             hi.w = 6.0f;

        // row start (r * 128000B) and base*4 are 32B-aligned -> full sector
        float4* p4 = (float4*)((float*)dst + base);
        p4[0] = lo;
        p4[1] = hi;
    }
}

extern "C" void kernel_launch(void* const* d_in, const int* in_sizes, int n_in,
                              void* d_out, int out_size) {
    (void)in_sizes; (void)n_in; (void)out_size;
    const int* ids = (const int*)d_in[0];

    majority_kernel<<<BSZ, MAJ_THREADS>>>(ids);

    // Fill with programmatic dependent launch: overlaps with majority_kernel,
    // each block waits via cudaGridDependencySynchronize before patching.
    cudaLaunchConfig_t cfg = {};
    cfg.gridDim  = dim3(FILL_BLOCKS, 1, 1);
    cfg.blockDim = dim3(THREADS, 1, 1);
    cfg.dynamicSmemBytes = 0;
    cfg.stream = 0;   // same (legacy) stream the harness captures

    cudaLaunchAttribute attr[1];
    attr[0].id = cudaLaunchAttributeProgrammaticStreamSerialization;
    attr[0].val.programmaticStreamSerializationAllowed = 1;
    cfg.attrs = attr;
    cfg.numAttrs = 1;

    cudaLaunchKernelEx(&cfg, fill_kernel, (float4*)d_out);
}

// round 13
// speedup vs baseline: 1.0128x; 1.0128x over previous
#include <cuda_runtime.h>
#include <cstddef>

#define BSZ 8
#define SEQLEN 2048
#define VOCAB 32000
#define BOS 1
#define V4 (VOCAB / 4)               // 8000 float4 per row
#define FILL_BLOCKS (BSZ * SEQLEN)   // 16384 rows, one block each
#define THREADS 256
#define MAJ_THREADS 1024
#define SMEM_HIST_BYTES (VOCAB * 4)  // 125 KB, fits 227 KB dynamic smem

// Result scratch (allocation-free rule: __device__ globals only)
__device__ int g_pred[BSZ];

// ---------------------------------------------------------------------------
// Kernel A: per-batch majority with a SHARED-MEMORY histogram (125 KB).
// Replaces the 2 MB global hist zero+rescan (8-SM bandwidth-bound) with
// STS zeroing + spread ATOMS + LDS scan -> ~2us. Triggers PDL completion at
// entry so the fill grid launches and streams concurrently.
// ---------------------------------------------------------------------------
__global__ __launch_bounds__(MAJ_THREADS) void majority_kernel(const int* __restrict__ ids) {
#if __CUDA_ARCH__ >= 900
    cudaTriggerProgrammaticLaunchCompletion();   // let fill grid launch now
#endif
    extern __shared__ int hist[];                // VOCAB ints
    const int b = blockIdx.x;
    const int t = threadIdx.x;

    // zero smem histogram: 32000 / 1024 = ~31 STS iters
    #pragma unroll 8
    for (int v = t; v < VOCAB; v += MAJ_THREADS) hist[v] = 0;
    __syncthreads();

    // accumulate valid tokens (exclude pad=0 and BOS=1): 2 per thread,
    // spread-address smem atomics (~2 cyc/lane)
    const int* row = ids + (size_t)b * SEQLEN;
    #pragma unroll 2
    for (int s = t; s < SEQLEN; s += MAJ_THREADS) {
        int tok = row[s];
        if (tok != 0 && tok != BOS) atomicAdd(&hist[tok], 1);
    }
    __syncthreads();

    // argmax, tie -> lowest index: key = (count<<15) | (32767 - v)
    __shared__ int best;
    if (t == 0) best = 0;
    __syncthreads();

    int lb = 0;
    #pragma unroll 8
    for (int v = t; v < VOCAB; v += MAJ_THREADS) {
        int key = (hist[v] << 15) | (32767 - v);
        lb = max(lb, key);
    }
    atomicMax(&best, lb);
    __syncthreads();

    if (t == 0) {
        int cnt = best >> 15;
        int v = 32767 - (best & 32767);
        g_pred[b] = (cnt > 0) ? v : BOS;  // no valid tokens -> BOS
    }
}

// ---------------------------------------------------------------------------
// Kernel B (UNCHANGED from R8 winner — proven 93.6% DRAM): streaming fill,
// one (b,s) row per block. Pure -6 STG.128 stream (no cache hints, no
// atomics, no fences), then HW-backed PDL wait, then thread 0 rewrites the
// aligned 32B sector holding the pred element (full-sector write, no RMW).
// ---------------------------------------------------------------------------
__global__ __launch_bounds__(THREADS) void fill_kernel(float4* __restrict__ out) {
    const int r = blockIdx.x;            // row index in [0, 16384)
    const int t = threadIdx.x;
    const int b = r >> 11;               // batch = r / SEQLEN

    const float4 neg = make_float4(-6.0f, -6.0f, -6.0f, -6.0f);
    float4* __restrict__ dst = out + (size_t)r * V4;

    for (int i = t; i < V4; i += THREADS) {
        dst[i] = neg;
    }

#if __CUDA_ARCH__ >= 900
    cudaGridDependencySynchronize();     // majority grid complete + visible
#endif
    __syncthreads();                     // order own -6 stores before patch

    if (t == 0) {
        const int p    = g_pred[b];
        const int base = p & ~7;         // 8-float (32B) aligned window
        const int c    = p & 7;

        float4 lo = neg, hi = neg;
        if      (c == 0) lo.x = 6.0f;
        else if (c == 1) lo.y = 6.0f;
        else if (c == 2) lo.z = 6.0f;
        else if (c == 3) lo.w = 6.0f;
        else if (c == 4) hi.x = 6.0f;
        else if (c == 5) hi.y = 6.0f;
        else if (c == 6) hi.z = 6.0f;
        else             hi.w = 6.0f;

        // row start (r * 128000B) and base*4 are 32B-aligned -> full sector
        float4* p4 = (float4*)((float*)dst + base);
        p4[0] = lo;
        p4[1] = hi;
    }
}

extern "C" void kernel_launch(void* const* d_in, const int* in_sizes, int n_in,
                              void* d_out, int out_size) {
    (void)in_sizes; (void)n_in; (void)out_size;
    const int* ids = (const int*)d_in[0];

    // raise dynamic smem limit for the 125 KB histogram (host attr set,
    // not a stream op — safe under graph capture; idempotent/deterministic)
    cudaFuncSetAttribute(majority_kernel,
                         cudaFuncAttributeMaxDynamicSharedMemorySize,
                         SMEM_HIST_BYTES);

    majority_kernel<<<BSZ, MAJ_THREADS, SMEM_HIST_BYTES>>>(ids);

    // Fill with programmatic dependent launch: overlaps with majority_kernel,
    // each block waits via cudaGridDependencySynchronize before patching.
    cudaLaunchConfig_t cfg = {};
    cfg.gridDim  = dim3(FILL_BLOCKS, 1, 1);
    cfg.blockDim = dim3(THREADS, 1, 1);
    cfg.dynamicSmemBytes = 0;
    cfg.stream = 0;   // same (legacy) stream the harness captures

    cudaLaunchAttribute attr[1];
    attr[0].id = cudaLaunchAttributeProgrammaticStreamSerialization;
    attr[0].val.programmaticStreamSerializationAllowed = 1;
    cfg.attrs = attr;
    cfg.numAttrs = 1;

    cudaLaunchKernelEx(&cfg, fill_kernel, (float4*)d_out);
}

// round 16
// speedup vs baseline: 1.0141x; 1.0013x over previous
#include <cuda_runtime.h>
#include <cstddef>

#define BSZ 8
#define SEQLEN 2048
#define VOCAB 32000
#define BOS 1
#define V4 (VOCAB / 4)               // 8000 float4 per row
#define FILL_BLOCKS (BSZ * SEQLEN)   // 16384 rows, one block each
#define THREADS 256
#define MAJ_THREADS 1024
#define SMEM_HIST_BYTES (VOCAB * 4)  // 125 KB, fits 227 KB dynamic smem

// Result scratch (allocation-free rule: __device__ globals only)
__device__ int g_pred[BSZ];

// ---------------------------------------------------------------------------
// Kernel A: per-batch majority, smem histogram, fully vectorized:
//   - zero: 8 x STS.128 per thread
//   - accumulate: int4 token loads + spread ATOMS
//   - scan: 8 x LDS.128 per thread, 4-wide key max
// Triggers PDL completion at entry so the fill grid launches immediately.
// ---------------------------------------------------------------------------
__global__ __launch_bounds__(MAJ_THREADS) void majority_kernel(const int* __restrict__ ids) {
#if __CUDA_ARCH__ >= 900
    cudaTriggerProgrammaticLaunchCompletion();   // let fill grid launch now
#endif
    extern __shared__ int hist[];                // VOCAB ints (16B aligned)
    int4* __restrict__ hist4 = (int4*)hist;      // 8000 int4
    const int b = blockIdx.x;
    const int t = threadIdx.x;

    // zero smem histogram: 8000 int4 / 1024 threads = 8 STS.128 iters
    const int4 z4 = make_int4(0, 0, 0, 0);
    #pragma unroll
    for (int i = 0; i < 8; i++) {
        int v = t + i * MAJ_THREADS;
        if (v < VOCAB / 4) hist4[v] = z4;
    }
    __syncthreads();

    // accumulate valid tokens (exclude pad=0 and BOS=1): 512 int4 loads
    const int4* row4 = (const int4*)(ids + (size_t)b * SEQLEN);
    if (t < SEQLEN / 4) {
        int4 tk = row4[t];
        if (tk.x != 0 && tk.x != BOS) atomicAdd(&hist[tk.x], 1);
        if (tk.y != 0 && tk.y != BOS) atomicAdd(&hist[tk.y], 1);
        if (tk.z != 0 && tk.z != BOS) atomicAdd(&hist[tk.z], 1);
        if (tk.w != 0 && tk.w != BOS) atomicAdd(&hist[tk.w], 1);
    }
    __syncthreads();

    // argmax, tie -> lowest index: key = (count<<15) | (32767 - v)
    __shared__ int best;
    if (t == 0) best = 0;
    __syncthreads();

    int lb = 0;
    #pragma unroll
    for (int i = 0; i < 8; i++) {
        int v4 = t + i * MAJ_THREADS;
        if (v4 < VOCAB / 4) {
            int4 c = hist4[v4];              // LDS.128
            int v = v4 * 4;
            int k0 = (c.x << 15) | (32767 - v);
            int k1 = (c.y << 15) | (32766 - v);
            int k2 = (c.z << 15) | (32765 - v);
            int k3 = (c.w << 15) | (32764 - v);
            lb = max(lb, max(max(k0, k1), max(k2, k3)));
        }
    }
    atomicMax(&best, lb);
    __syncthreads();

    if (t == 0) {
        int cnt = best >> 15;
        int v = 32767 - (best & 32767);
        g_pred[b] = (cnt > 0) ? v : BOS;     // no valid tokens -> BOS
    }
}

// ---------------------------------------------------------------------------
// Kernel B (UNCHANGED from R8/R12 winner — proven 93%+ DRAM): streaming fill,
// one (b,s) row per block. Pure -6 STG.128 stream (no cache hints, no
// atomics, no fences), then HW-backed PDL wait, then thread 0 rewrites the
// aligned 32B sector holding the pred element (full-sector write, no RMW).
// ---------------------------------------------------------------------------
__global__ __launch_bounds__(THREADS) void fill_kernel(float4* __restrict__ out) {
    const int r = blockIdx.x;            // row index in [0, 16384)
    const int t = threadIdx.x;
    const int b = r >> 11;               // batch = r / SEQLEN

    const float4 neg = make_float4(-6.0f, -6.0f, -6.0f, -6.0f);
    float4* __restrict__ dst = out + (size_t)r * V4;

    for (int i = t; i < V4; i += THREADS) {
        dst[i] = neg;
    }

#if __CUDA_ARCH__ >= 900
    cudaGridDependencySynchronize();     // majority grid complete + visible
#endif
    __syncthreads();                     // order own -6 stores before patch

    if (t == 0) {
        const int p    = g_pred[b];
        const int base = p & ~7;         // 8-float (32B) aligned window
        const int c    = p & 7;

        float4 lo = neg, hi = neg;
        if      (c == 0) lo.x = 6.0f;
        else if (c == 1) lo.y = 6.0f;
        else if (c == 2) lo.z = 6.0f;
        else if (c == 3) lo.w = 6.0f;
        else if (c == 4) hi.x = 6.0f;
        else if (c == 5) hi.y = 6.0f;
        else if (c == 6) hi.z = 6.0f;
        else             hi.w = 6.0f;

        // row start (r * 128000B) and base*4 are 32B-aligned -> full sector
        float4* p4 = (float4*)((float*)dst + base);
        p4[0] = lo;
        p4[1] = hi;
    }
}

extern "C" void kernel_launch(void* const* d_in, const int* in_sizes, int n_in,
                              void* d_out, int out_size) {
    (void)in_sizes; (void)n_in; (void)out_size;
    const int* ids = (const int*)d_in[0];

    // raise dynamic smem limit for the 125 KB histogram (host attr set,
    // not a stream op — safe under graph capture; idempotent/deterministic)
    cudaFuncSetAttribute(majority_kernel,
                         cudaFuncAttributeMaxDynamicSharedMemorySize,
                         SMEM_HIST_BYTES);

    majority_kernel<<<BSZ, MAJ_THREADS, SMEM_HIST_BYTES>>>(ids);

    // Fill with programmatic dependent launch: overlaps with majority_kernel,
    // each block waits via cudaGridDependencySynchronize before patching.
    cudaLaunchConfig_t cfg = {};
    cfg.gridDim  = dim3(FILL_BLOCKS, 1, 1);
    cfg.blockDim = dim3(THREADS, 1, 1);
    cfg.dynamicSmemBytes = 0;
    cfg.stream = 0;   // same (legacy) stream the harness captures

    cudaLaunchAttribute attr[1];
    attr[0].id = cudaLaunchAttributeProgrammaticStreamSerialization;
    attr[0].val.programmaticStreamSerializationAllowed = 1;
    cfg.attrs = attr;
    cfg.numAttrs = 1;

    cudaLaunchKernelEx(&cfg, fill_kernel, (float4*)d_out);
}